// round 7
// baseline (speedup 1.0000x reference)
#include <cuda_runtime.h>
#include <cuda_bf16.h>
#include <math.h>

#define T_SEQ   2048
#define BATCH   2
#define DM      1024
#define NH      16
#define DH      64
#define MROWS   (BATCH*T_SEQ)    /* 4096 */
#define N_QKV   (3*DM)           /* 3072 */
#define KW      (DM/2)           /* 512 words per row (bf16 pairs) */

// ---------------------------------------------------------------------------
// Pre-split bf16 hi/lo storage (allocation-free rule: __device__ globals).
// Layout: [row][kpair-word]; word = packed bf16x2 (even k low, odd k high).
// ---------------------------------------------------------------------------
__device__ unsigned g_Xh[MROWS*KW],  g_Xl[MROWS*KW];     // X split
__device__ unsigned g_Wqh[N_QKV*KW], g_Wql[N_QKV*KW];    // W_qkv^T split
__device__ unsigned g_Wph[DM*KW],    g_Wpl[DM*KW];       // W_proj^T split
__device__ unsigned g_Qh[MROWS*DM/2], g_Ql[MROWS*DM/2];  // [b,h,t][32 words], pre-scaled
__device__ unsigned g_Kh[MROWS*DM/2], g_Kl[MROWS*DM/2];
__device__ float    g_V[MROWS*DM];                       // [b,h,t][64] fp32
__device__ unsigned g_Ah[MROWS*KW],  g_Al[MROWS*KW];     // attn out split

// ---------------------------------------------------------------------------
__device__ __forceinline__ void split2(float a, float b, unsigned &hi, unsigned &lo)
{
    __nv_bfloat16 ha = __float2bfloat16_rn(a);
    __nv_bfloat16 hb = __float2bfloat16_rn(b);
    __nv_bfloat162 h; h.x = ha; h.y = hb;
    hi = *reinterpret_cast<unsigned*>(&h);
    __nv_bfloat162 l = __floats2bfloat162_rn(a - __bfloat162float(ha),
                                             b - __bfloat162float(hb));
    lo = *reinterpret_cast<unsigned*>(&l);
}

__device__ __forceinline__ void mma16816(float* d,
    unsigned a0, unsigned a1, unsigned a2, unsigned a3,
    unsigned b0, unsigned b1)
{
    asm volatile(
        "mma.sync.aligned.m16n8k16.row.col.f32.bf16.bf16.f32 "
        "{%0,%1,%2,%3}, {%4,%5,%6,%7}, {%8,%9}, {%0,%1,%2,%3};\n"
        : "+f"(d[0]), "+f"(d[1]), "+f"(d[2]), "+f"(d[3])
        : "r"(a0), "r"(a1), "r"(a2), "r"(a3), "r"(b0), "r"(b1));
}

__device__ __forceinline__ void cp16(unsigned* dst_smem, const unsigned* src)
{
    unsigned d = (unsigned)__cvta_generic_to_shared(dst_smem);
    asm volatile("cp.async.cg.shared.global [%0], [%1], 16;\n" :: "r"(d), "l"(src));
}
__device__ __forceinline__ void cp_commit() { asm volatile("cp.async.commit_group;\n"); }
template<int N> __device__ __forceinline__ void cp_wait()
{ asm volatile("cp.async.wait_group %0;\n" :: "n"(N)); }

// ---------------------------------------------------------------------------
// Prep 1: elementwise split of a row-major fp32 matrix (pairs along k).
// Each thread: 4 words (8 floats).
// ---------------------------------------------------------------------------
__global__ __launch_bounds__(256)
void split_rows_kernel(const float* __restrict__ src,
                       unsigned* __restrict__ dh, unsigned* __restrict__ dl)
{
    const int gt = blockIdx.x * 256 + threadIdx.x;
    const float4* s4 = (const float4*)src;
    float4 v0 = s4[gt * 2];
    float4 v1 = s4[gt * 2 + 1];
    unsigned h, l;
    const int o = gt * 4;
    split2(v0.x, v0.y, h, l); dh[o]     = h; dl[o]     = l;
    split2(v0.z, v0.w, h, l); dh[o + 1] = h; dl[o + 1] = l;
    split2(v1.x, v1.y, h, l); dh[o + 2] = h; dl[o + 2] = l;
    split2(v1.z, v1.w, h, l); dh[o + 3] = h; dl[o + 3] = l;
}

// ---------------------------------------------------------------------------
// Prep 2: transpose+split W[k][N] -> Wh/Wl [n][KW]. 64x64 tiles, 256 threads.
// ---------------------------------------------------------------------------
__global__ __launch_bounds__(256)
void wsplit_kernel(const float* __restrict__ W,
                   unsigned* __restrict__ wh, unsigned* __restrict__ wl, int N)
{
    __shared__ float sw[64][68];
    const int tid = threadIdx.x;
    const int k0 = blockIdx.x * 64;
    const int n0 = blockIdx.y * 64;

#pragma unroll
    for (int i = 0; i < 4; i++) {
        const int row = (tid >> 4) + i * 16;
        const int col = (tid & 15) * 4;
        float4 v = *(const float4*)&W[(size_t)(k0 + row) * N + n0 + col];
        *(float4*)&sw[row][col] = v;
    }
    __syncthreads();

    const int n  = tid & 63;
    const int kb = (tid >> 6) * 8;
#pragma unroll
    for (int j = 0; j < 8; j++) {
        const int kp = kb + j;
        unsigned h, l;
        split2(sw[2 * kp][n], sw[2 * kp + 1][n], h, l);
        const size_t o = (size_t)(n0 + n) * KW + (k0 >> 1) + kp;
        wh[o] = h; wl[o] = l;
    }
}

// ---------------------------------------------------------------------------
// Tensor-core GEMM v2: pre-split operands, cp.async double-buffered staging.
// Block 128x128x32, 8 warps (2x4), warp tile 64x32. 3-MMA bf16 split.
// smem: 2 buffers x (Ahi|Alo|Bhi|Blo) x 128*20 words = 81920 B.
// ---------------------------------------------------------------------------
__device__ __forceinline__ void gemm_stage(unsigned* base,
    const unsigned* Ah, const unsigned* Al,
    const unsigned* Bh, const unsigned* Bl,
    int m0, int n0, int i, int tid)
{
    const int cr = tid >> 1;
    const int ch = (tid & 1) * 8;
    const size_t as = (size_t)(m0 + cr) * KW + i * 16 + ch;
    const size_t bs = (size_t)(n0 + cr) * KW + i * 16 + ch;
    unsigned* d = base + cr * 20 + ch;
    cp16(d,            Ah + as); cp16(d + 4,        Ah + as + 4);
    cp16(d + 2560,     Al + as); cp16(d + 2560 + 4, Al + as + 4);
    cp16(d + 5120,     Bh + bs); cp16(d + 5120 + 4, Bh + bs + 4);
    cp16(d + 7680,     Bl + bs); cp16(d + 7680 + 4, Bl + bs + 4);
}

template<bool SCATTER>
__global__ __launch_bounds__(256, 2)
void mma_gemm2(const unsigned* __restrict__ Ah, const unsigned* __restrict__ Al,
               const unsigned* __restrict__ Bh, const unsigned* __restrict__ Bl,
               const float* __restrict__ bias, float* __restrict__ out)
{
    extern __shared__ unsigned sg[];

    const int tid  = threadIdx.x;
    const int lane = tid & 31;
    const int warp = tid >> 5;
    const int wm   = warp >> 2;
    const int wn   = warp & 3;
    const int g    = lane >> 2;
    const int t    = lane & 3;
    const int m0   = blockIdx.y * 128;
    const int n0   = blockIdx.x * 128;

    float acc[4][4][4];
#pragma unroll
    for (int mt = 0; mt < 4; mt++)
#pragma unroll
        for (int nt = 0; nt < 4; nt++)
#pragma unroll
            for (int i = 0; i < 4; i++) acc[mt][nt][i] = 0.f;

    gemm_stage(sg, Ah, Al, Bh, Bl, m0, n0, 0, tid);
    cp_commit();

    for (int i = 0; i < 32; i++) {
        if (i + 1 < 32) {
            gemm_stage(sg + ((i + 1) & 1) * 10240, Ah, Al, Bh, Bl, m0, n0, i + 1, tid);
            cp_commit();
            cp_wait<1>();
        } else {
            cp_wait<0>();
        }
        __syncthreads();

        const unsigned* Ahi = sg + (i & 1) * 10240;
        const unsigned* Alo = Ahi + 2560;
        const unsigned* Bhi = Ahi + 5120;
        const unsigned* Blo = Ahi + 7680;

#pragma unroll
        for (int ks = 0; ks < 2; ks++) {
            unsigned ah[4][4], al[4][4], bh[4][2], bl[4][2];
#pragma unroll
            for (int mt = 0; mt < 4; mt++) {
                const int base = (wm * 64 + mt * 16 + g) * 20 + ks * 8 + t;
                ah[mt][0] = Ahi[base];       ah[mt][1] = Ahi[base + 160];
                ah[mt][2] = Ahi[base + 4];   ah[mt][3] = Ahi[base + 164];
                al[mt][0] = Alo[base];       al[mt][1] = Alo[base + 160];
                al[mt][2] = Alo[base + 4];   al[mt][3] = Alo[base + 164];
            }
#pragma unroll
            for (int nt = 0; nt < 4; nt++) {
                const int base = (wn * 32 + nt * 8 + g) * 20 + ks * 8 + t;
                bh[nt][0] = Bhi[base];       bh[nt][1] = Bhi[base + 4];
                bl[nt][0] = Blo[base];       bl[nt][1] = Blo[base + 4];
            }
#pragma unroll
            for (int mt = 0; mt < 4; mt++)
#pragma unroll
                for (int nt = 0; nt < 4; nt++) {
                    mma16816(acc[mt][nt], ah[mt][0], ah[mt][1], ah[mt][2], ah[mt][3],
                             bh[nt][0], bh[nt][1]);
                    mma16816(acc[mt][nt], ah[mt][0], ah[mt][1], ah[mt][2], ah[mt][3],
                             bl[nt][0], bl[nt][1]);
                    mma16816(acc[mt][nt], al[mt][0], al[mt][1], al[mt][2], al[mt][3],
                             bh[nt][0], bh[nt][1]);
                }
        }
        __syncthreads();
    }

    // ---- epilogue ----
#pragma unroll
    for (int mt = 0; mt < 4; mt++) {
        const int mrow0 = m0 + wm * 64 + mt * 16 + g;
#pragma unroll
        for (int nt = 0; nt < 4; nt++) {
            const int c = n0 + wn * 32 + nt * 8 + 2 * t;
            const float b0 = bias[c], b1 = bias[c + 1];
            const float v00 = acc[mt][nt][0] + b0;
            const float v01 = acc[mt][nt][1] + b1;
            const float v10 = acc[mt][nt][2] + b0;
            const float v11 = acc[mt][nt][3] + b1;
            if (SCATTER) {
                const int which = c >> 10;                 // 0=Q 1=K 2=V
                const int cc = c & (DM - 1);
                const int h  = cc >> 6;
                const int d  = cc & (DH - 1);              // even
#pragma unroll
                for (int rr = 0; rr < 2; rr++) {
                    const int m   = mrow0 + rr * 8;
                    const int bb  = m >> 11;
                    const int tok = m & (T_SEQ - 1);
                    const size_t row = (size_t)(bb * NH + h) * T_SEQ + tok;
                    const float a = rr ? v10 : v00;
                    const float b = rr ? v11 : v01;
                    if (which == 0) {               // Q pre-scaled 1/sqrt(Dh)
                        unsigned h_, l_;
                        split2(a * 0.125f, b * 0.125f, h_, l_);
                        g_Qh[row * 32 + (d >> 1)] = h_;
                        g_Ql[row * 32 + (d >> 1)] = l_;
                    } else if (which == 1) {        // K
                        unsigned h_, l_;
                        split2(a, b, h_, l_);
                        g_Kh[row * 32 + (d >> 1)] = h_;
                        g_Kl[row * 32 + (d >> 1)] = l_;
                    } else {                        // V fp32
                        *(float2*)&g_V[row * DH + d] = make_float2(a, b);
                    }
                }
            } else {
                *(float2*)&out[(size_t)mrow0 * DM + c]       = make_float2(v00, v01);
                *(float2*)&out[(size_t)(mrow0 + 8) * DM + c] = make_float2(v10, v11);
            }
        }
    }
}

// ---------------------------------------------------------------------------
// Attention v3: 128-row Q tiles, 8 warps; Q/K pre-split (cp.async staging);
// V fp32 staged transposed with split; P in registers (S C-frag == P A-frag).
// smem stride 36 words/row -> conflict-free fragment LDS.
// ---------------------------------------------------------------------------
#define ASTR 36
__global__ __launch_bounds__(256, 2)
void attn_mma3()
{
    extern __shared__ unsigned smu[];
    unsigned* sQh = smu;                     // 128*36
    unsigned* sQl = smu + 128 * ASTR;
    unsigned* sKh = smu + 2 * 128 * ASTR;    // 64*36
    unsigned* sKl = sKh + 64 * ASTR;
    unsigned* sVh = sKl + 64 * ASTR;
    unsigned* sVl = sVh + 64 * ASTR;

    const int tid  = threadIdx.x;
    const int lane = tid & 31;
    const int w    = tid >> 5;      // warp 0..7, rows 16w..16w+15
    const int g    = lane >> 2;
    const int t    = lane & 3;
    const int qt   = (int)(gridDim.x - 1) - (int)blockIdx.x;  // longest first
    const int bh   = blockIdx.y;
    const int q0   = qt * 128;

    const unsigned* Qh = g_Qh + (size_t)bh * T_SEQ * 32;
    const unsigned* Ql = g_Ql + (size_t)bh * T_SEQ * 32;
    const unsigned* Kh = g_Kh + (size_t)bh * T_SEQ * 32;
    const unsigned* Kl = g_Kl + (size_t)bh * T_SEQ * 32;
    const float*    Vg = g_V  + (size_t)bh * T_SEQ * DH;

    // stage Q once (cp.async; group drains at first iter's wait)
    {
        const int r   = tid >> 1;
        const int off = (tid & 1) * 16;
        const unsigned* s = Qh + (size_t)(q0 + r) * 32 + off;
        unsigned* d = sQh + r * ASTR + off;
        cp16(d, s); cp16(d + 4, s + 4); cp16(d + 8, s + 8); cp16(d + 12, s + 12);
        s = Ql + (size_t)(q0 + r) * 32 + off;
        d = sQl + r * ASTR + off;
        cp16(d, s); cp16(d + 4, s + 4); cp16(d + 8, s + 8); cp16(d + 12, s + 12);
    }
    cp_commit();

    float oacc[8][4];
#pragma unroll
    for (int nf = 0; nf < 8; nf++)
#pragma unroll
        for (int i = 0; i < 4; i++) oacc[nf][i] = 0.f;
    float mrun0 = -INFINITY, mrun1 = -INFINITY;
    float lrun0 = 0.f, lrun1 = 0.f;

    const int ntiles = 2 * qt + 2;
    for (int kt = 0; kt < ntiles; kt++) {
        const int k0 = kt * 64;
        __syncthreads();   // prior compute done reading smem

        // K via cp.async (overlaps with V work below)
        {
            const int r   = tid >> 2;
            const int off = (tid & 3) * 8;
            const unsigned* s = Kh + (size_t)(k0 + r) * 32 + off;
            unsigned* d = sKh + r * ASTR + off;
            cp16(d, s); cp16(d + 4, s + 4);
            s = Kl + (size_t)(k0 + r) * 32 + off;
            d = sKl + r * ASTR + off;
            cp16(d, s); cp16(d + 4, s + 4);
        }
        cp_commit();

        // V: fp32 load, split, transposed store [d][keypair]
        {
            const int r  = tid & 31;          // keypair
            const int dc = (tid >> 5) * 8;    // d base
            const float* p0 = &Vg[(size_t)(k0 + 2 * r) * DH + dc];
            float4 a0 = *(const float4*)p0;
            float4 a1 = *(const float4*)(p0 + 4);
            float4 b0 = *(const float4*)(p0 + DH);
            float4 b1 = *(const float4*)(p0 + DH + 4);
            unsigned h, l;
            split2(a0.x, b0.x, h, l); sVh[(dc + 0) * ASTR + r] = h; sVl[(dc + 0) * ASTR + r] = l;
            split2(a0.y, b0.y, h, l); sVh[(dc + 1) * ASTR + r] = h; sVl[(dc + 1) * ASTR + r] = l;
            split2(a0.z, b0.z, h, l); sVh[(dc + 2) * ASTR + r] = h; sVl[(dc + 2) * ASTR + r] = l;
            split2(a0.w, b0.w, h, l); sVh[(dc + 3) * ASTR + r] = h; sVl[(dc + 3) * ASTR + r] = l;
            split2(a1.x, b1.x, h, l); sVh[(dc + 4) * ASTR + r] = h; sVl[(dc + 4) * ASTR + r] = l;
            split2(a1.y, b1.y, h, l); sVh[(dc + 5) * ASTR + r] = h; sVl[(dc + 5) * ASTR + r] = l;
            split2(a1.z, b1.z, h, l); sVh[(dc + 6) * ASTR + r] = h; sVl[(dc + 6) * ASTR + r] = l;
            split2(a1.w, b1.w, h, l); sVh[(dc + 7) * ASTR + r] = h; sVl[(dc + 7) * ASTR + r] = l;
        }
        cp_wait<0>();
        __syncthreads();

        // warp fully above the diagonal for this tile? (rows < all cols)
        const bool active = (k0 <= q0 + 16 * w + 15);
        if (active) {
            // ---- S = Q K^T ----
            float sacc[8][4];
#pragma unroll
            for (int nf = 0; nf < 8; nf++)
#pragma unroll
                for (int i = 0; i < 4; i++) sacc[nf][i] = 0.f;

#pragma unroll
            for (int ks = 0; ks < 4; ks++) {
                const int qb = (16 * w + g) * ASTR + ks * 8 + t;
                const unsigned qh0 = sQh[qb],     qh1 = sQh[qb + 8 * ASTR];
                const unsigned qh2 = sQh[qb + 4], qh3 = sQh[qb + 8 * ASTR + 4];
                const unsigned ql0 = sQl[qb],     ql1 = sQl[qb + 8 * ASTR];
                const unsigned ql2 = sQl[qb + 4], ql3 = sQl[qb + 8 * ASTR + 4];
#pragma unroll
                for (int nf = 0; nf < 8; nf++) {
                    const int kb = (8 * nf + g) * ASTR + ks * 8 + t;
                    const unsigned kh0 = sKh[kb], kh1 = sKh[kb + 4];
                    const unsigned kl0 = sKl[kb], kl1 = sKl[kb + 4];
                    mma16816(sacc[nf], qh0, qh1, qh2, qh3, kh0, kh1);
                    mma16816(sacc[nf], qh0, qh1, qh2, qh3, kl0, kl1);
                    mma16816(sacc[nf], ql0, ql1, ql2, ql3, kh0, kh1);
                }
            }

            // ---- causal mask (only near-diagonal tiles) ----
            if (k0 + 63 > q0 + 16 * w) {
                const int r0g = q0 + 16 * w + g, r1g = r0g + 8;
#pragma unroll
                for (int nf = 0; nf < 8; nf++) {
                    const int c = k0 + 8 * nf + 2 * t;
                    if (c     > r0g) sacc[nf][0] = -INFINITY;
                    if (c + 1 > r0g) sacc[nf][1] = -INFINITY;
                    if (c     > r1g) sacc[nf][2] = -INFINITY;
                    if (c + 1 > r1g) sacc[nf][3] = -INFINITY;
                }
            }

            // ---- online softmax ----
            float rm0 = -INFINITY, rm1 = -INFINITY;
#pragma unroll
            for (int nf = 0; nf < 8; nf++) {
                rm0 = fmaxf(rm0, fmaxf(sacc[nf][0], sacc[nf][1]));
                rm1 = fmaxf(rm1, fmaxf(sacc[nf][2], sacc[nf][3]));
            }
            rm0 = fmaxf(rm0, __shfl_xor_sync(0xffffffffu, rm0, 1));
            rm0 = fmaxf(rm0, __shfl_xor_sync(0xffffffffu, rm0, 2));
            rm1 = fmaxf(rm1, __shfl_xor_sync(0xffffffffu, rm1, 1));
            rm1 = fmaxf(rm1, __shfl_xor_sync(0xffffffffu, rm1, 2));

            const float mn0 = fmaxf(mrun0, rm0);
            const float mn1 = fmaxf(mrun1, rm1);
            const float c0  = __expf(mrun0 - mn0);
            const float c1  = __expf(mrun1 - mn1);

            float rs0 = 0.f, rs1 = 0.f;
#pragma unroll
            for (int nf = 0; nf < 8; nf++) {
                sacc[nf][0] = __expf(sacc[nf][0] - mn0); rs0 += sacc[nf][0];
                sacc[nf][1] = __expf(sacc[nf][1] - mn0); rs0 += sacc[nf][1];
                sacc[nf][2] = __expf(sacc[nf][2] - mn1); rs1 += sacc[nf][2];
                sacc[nf][3] = __expf(sacc[nf][3] - mn1); rs1 += sacc[nf][3];
            }
            rs0 += __shfl_xor_sync(0xffffffffu, rs0, 1);
            rs0 += __shfl_xor_sync(0xffffffffu, rs0, 2);
            rs1 += __shfl_xor_sync(0xffffffffu, rs1, 1);
            rs1 += __shfl_xor_sync(0xffffffffu, rs1, 2);

            lrun0 = lrun0 * c0 + rs0;
            lrun1 = lrun1 * c1 + rs1;
            mrun0 = mn0;
            mrun1 = mn1;
#pragma unroll
            for (int nf = 0; nf < 8; nf++) {
                oacc[nf][0] *= c0; oacc[nf][1] *= c0;
                oacc[nf][2] *= c1; oacc[nf][3] *= c1;
            }

            // ---- O += P V (S C-frags ARE P A-frags) ----
#pragma unroll
            for (int ks = 0; ks < 4; ks++) {
                unsigned ph0, pl0, ph1, pl1, ph2, pl2, ph3, pl3;
                split2(sacc[2 * ks][0],     sacc[2 * ks][1],     ph0, pl0);
                split2(sacc[2 * ks][2],     sacc[2 * ks][3],     ph1, pl1);
                split2(sacc[2 * ks + 1][0], sacc[2 * ks + 1][1], ph2, pl2);
                split2(sacc[2 * ks + 1][2], sacc[2 * ks + 1][3], ph3, pl3);
#pragma unroll
                for (int nf = 0; nf < 8; nf++) {
                    const int vb = (8 * nf + g) * ASTR + ks * 8 + t;
                    const unsigned vh0 = sVh[vb], vh1 = sVh[vb + 4];
                    const unsigned vl0 = sVl[vb], vl1 = sVl[vb + 4];
                    mma16816(oacc[nf], ph0, ph1, ph2, ph3, vh0, vh1);
                    mma16816(oacc[nf], ph0, ph1, ph2, ph3, vl0, vl1);
                    mma16816(oacc[nf], pl0, pl1, pl2, pl3, vh0, vh1);
                }
            }
        }
    }

    // ---- normalize; write pre-split to g_Ah/g_Al ([B,T] rows of kpairs) ----
    const float inv0 = 1.f / lrun0;
    const float inv1 = 1.f / lrun1;
    const int b  = bh >> 4;
    const int h  = bh & 15;
    const int r0 = q0 + 16 * w + g;
    const int r1 = r0 + 8;
#pragma unroll
    for (int nf = 0; nf < 8; nf++) {
        const int widx = h * 32 + 4 * nf + t;   // (h*64 + 8nf + 2t)/2
        unsigned hw, lw;
        split2(oacc[nf][0] * inv0, oacc[nf][1] * inv0, hw, lw);
        g_Ah[(size_t)(b * T_SEQ + r0) * KW + widx] = hw;
        g_Al[(size_t)(b * T_SEQ + r0) * KW + widx] = lw;
        split2(oacc[nf][2] * inv1, oacc[nf][3] * inv1, hw, lw);
        g_Ah[(size_t)(b * T_SEQ + r1) * KW + widx] = hw;
        g_Al[(size_t)(b * T_SEQ + r1) * KW + widx] = lw;
    }
}

// ---------------------------------------------------------------------------
extern "C" void kernel_launch(void* const* d_in, const int* in_sizes, int n_in,
                              void* d_out, int out_size)
{
    const float* x      = (const float*)d_in[0];
    const float* W_qkv  = (const float*)d_in[1];
    const float* b_qkv  = (const float*)d_in[2];
    const float* W_proj = (const float*)d_in[3];
    const float* b_proj = (const float*)d_in[4];
    float* out = (float*)d_out;

    (void)in_sizes; (void)n_in; (void)out_size;

    unsigned *Xh, *Xl, *Wqh, *Wql, *Wph, *Wpl, *Ah, *Al;
    cudaGetSymbolAddress((void**)&Xh,  g_Xh);
    cudaGetSymbolAddress((void**)&Xl,  g_Xl);
    cudaGetSymbolAddress((void**)&Wqh, g_Wqh);
    cudaGetSymbolAddress((void**)&Wql, g_Wql);
    cudaGetSymbolAddress((void**)&Wph, g_Wph);
    cudaGetSymbolAddress((void**)&Wpl, g_Wpl);
    cudaGetSymbolAddress((void**)&Ah,  g_Ah);
    cudaGetSymbolAddress((void**)&Al,  g_Al);

    const int gemm_smem = 2 * 4 * 128 * 20 * 4;   // 81920 B
    const int attn_smem = (2 * 128 + 4 * 64) * ASTR * 4;  // 73728 B
    cudaFuncSetAttribute(mma_gemm2<true>,
                         cudaFuncAttributeMaxDynamicSharedMemorySize, gemm_smem);
    cudaFuncSetAttribute(mma_gemm2<false>,
                         cudaFuncAttributeMaxDynamicSharedMemorySize, gemm_smem);
    cudaFuncSetAttribute(attn_mma3,
                         cudaFuncAttributeMaxDynamicSharedMemorySize, attn_smem);

    // prep: split X; transpose+split both W
    split_rows_kernel<<<MROWS * KW / (256 * 4), 256>>>(x, Xh, Xl);
    dim3 gw1(DM / 64, N_QKV / 64);
    wsplit_kernel<<<gw1, 256>>>(W_qkv, Wqh, Wql, N_QKV);
    dim3 gw2(DM / 64, DM / 64);
    wsplit_kernel<<<gw2, 256>>>(W_proj, Wph, Wpl, DM);

    dim3 gA(N_QKV / 128, MROWS / 128);   // (24, 32)
    mma_gemm2<true><<<gA, 256, gemm_smem>>>(Xh, Xl, Wqh, Wql, b_qkv, nullptr);

    dim3 gB(T_SEQ / 128, BATCH * NH);    // (16, 32)
    attn_mma3<<<gB, 256, attn_smem>>>();

    dim3 gC(DM / 128, MROWS / 128);      // (8, 32)
    mma_gemm2<false><<<gC, 256, gemm_smem>>>(Ah, Al, Wph, Wpl, b_proj, out);
}